// round 12
// baseline (speedup 1.0000x reference)
#include <cuda_runtime.h>
#include <cuda_fp16.h>
#include <math.h>
#include <stdint.h>

#define D_MODEL   2048
#define NUM_HEADS 16
#define HEAD      128
#define FAN       4
#define QKV_OUT   (3 * D_MODEL + FAN * D_MODEL)   // 14336
#define HIDDEN    (FAN * D_MODEL)                 // 8192
#define BB        2
#define TT        2048
#define BT        (BB * TT)                       // 4096
#define QKV3      (3 * D_MODEL)                   // 6144

// ---------------- scratch (device globals) ---------------------------------
__device__ float  g_attn[(size_t)BT * D_MODEL];   // attention output scratch
__device__ __half g_x[(size_t)BT * D_MODEL];
__device__ __half g_wq[(size_t)D_MODEL * QKV_OUT];
__device__ __half g_wm[(size_t)HIDDEN * D_MODEL];
__device__ __half g_h[(size_t)BT * HIDDEN];
// head-major [b][h][t][d] q/k/v for flash
__device__ __half g_q[(size_t)BT * D_MODEL];
__device__ __half g_k[(size_t)BT * D_MODEL];
__device__ __half g_v[(size_t)BT * D_MODEL];

// ---------------- PTX helpers ----------------------------------------------
__device__ __forceinline__ uint32_t smem_u32(const void* p) {
    uint32_t a;
    asm("{ .reg .u64 t; cvta.to.shared.u64 t, %1; cvt.u32.u64 %0, t; }"
        : "=r"(a) : "l"(p));
    return a;
}
__device__ __forceinline__ void cp16(uint32_t dst, const void* src) {
    asm volatile("cp.async.cg.shared.global [%0], [%1], 16;" :: "r"(dst), "l"(src));
}
#define CP_COMMIT() asm volatile("cp.async.commit_group;")
#define CP_WAIT0()  asm volatile("cp.async.wait_group 0;")
#define CP_WAIT1()  asm volatile("cp.async.wait_group 1;")
#define CP_WAIT2()  asm volatile("cp.async.wait_group 2;")

__device__ __forceinline__ void ldsm_x4(uint32_t& r0, uint32_t& r1,
                                        uint32_t& r2, uint32_t& r3, uint32_t addr) {
    asm volatile("ldmatrix.sync.aligned.m8n8.x4.shared.b16 {%0,%1,%2,%3}, [%4];"
                 : "=r"(r0), "=r"(r1), "=r"(r2), "=r"(r3) : "r"(addr));
}
__device__ __forceinline__ void ldsm_x4t(uint32_t& r0, uint32_t& r1,
                                         uint32_t& r2, uint32_t& r3, uint32_t addr) {
    asm volatile("ldmatrix.sync.aligned.m8n8.x4.trans.shared.b16 {%0,%1,%2,%3}, [%4];"
                 : "=r"(r0), "=r"(r1), "=r"(r2), "=r"(r3) : "r"(addr));
}
__device__ __forceinline__ void mma_f16(float* d,
                                        uint32_t a0, uint32_t a1, uint32_t a2, uint32_t a3,
                                        uint32_t b0, uint32_t b1) {
    asm volatile(
        "mma.sync.aligned.m16n8k16.row.col.f32.f16.f16.f32 "
        "{%0,%1,%2,%3}, {%4,%5,%6,%7}, {%8,%9}, {%0,%1,%2,%3};"
        : "+f"(d[0]), "+f"(d[1]), "+f"(d[2]), "+f"(d[3])
        : "r"(a0), "r"(a1), "r"(a2), "r"(a3), "r"(b0), "r"(b1));
}
__device__ __forceinline__ uint32_t pack_h(float x, float y) {
    __half2 h = __float22half2_rn(make_float2(x, y));
    return *(uint32_t*)&h;
}
// two exps in one MUFU op (fp16x2, base-2)
__device__ __forceinline__ uint32_t ex2_f16x2(float a, float b) {
    uint32_t in = pack_h(a, b), out;
    asm("ex2.approx.f16x2 %0, %1;" : "=r"(out) : "r"(in));
    return out;
}
__device__ __forceinline__ float ex2f(float x) {
    float y; asm("ex2.approx.f32 %0, %1;" : "=f"(y) : "f"(x)); return y;
}
__device__ __forceinline__ float warp_sum(float v) {
    #pragma unroll
    for (int o = 16; o > 0; o >>= 1) v += __shfl_xor_sync(0xffffffffu, v, o);
    return v;
}
__device__ __forceinline__ float gelu_f(float x) {
    return 0.5f * x * (1.f + erff(x * 0.70710678118654752f));
}

// ---------------- 0) fp32 -> fp16 convert (weights) -------------------------
__global__ void convert_kernel(const float* __restrict__ in, __half* __restrict__ oh) {
    int idx = blockIdx.x * blockDim.x + threadIdx.x;
    float4 v = ((const float4*)in)[idx];
    ((uint2*)oh)[idx] = make_uint2(pack_h(v.x, v.y), pack_h(v.z, v.w));
}

// ---------------- 1) LayerNorm(inputs) -> fp16 ------------------------------
__global__ void ln_input_kernel(const float* __restrict__ in, __half* __restrict__ oh) {
    int row = blockIdx.x;
    const float4* src = (const float4*)(in + (size_t)row * D_MODEL);

    float4 v[2];
    float s = 0.f, sq = 0.f;
    #pragma unroll
    for (int i = 0; i < 2; i++) {
        v[i] = src[threadIdx.x + i * 256];
        s  += v[i].x + v[i].y + v[i].z + v[i].w;
        sq += v[i].x * v[i].x + v[i].y * v[i].y + v[i].z * v[i].z + v[i].w * v[i].w;
    }
    __shared__ float sh_s[8], sh_q[8];
    int lane = threadIdx.x & 31, wid = threadIdx.x >> 5;
    s = warp_sum(s); sq = warp_sum(sq);
    if (lane == 0) { sh_s[wid] = s; sh_q[wid] = sq; }
    __syncthreads();
    if (wid == 0) {
        float a = (lane < 8) ? sh_s[lane] : 0.f;
        float b = (lane < 8) ? sh_q[lane] : 0.f;
        a = warp_sum(a); b = warp_sum(b);
        if (lane == 0) { sh_s[0] = a; sh_q[0] = b; }
    }
    __syncthreads();
    float mean = sh_s[0] * (1.f / D_MODEL);
    float var  = sh_q[0] * (1.f / D_MODEL) - mean * mean;
    float r    = rsqrtf(var + 1e-5f);
    #pragma unroll
    for (int i = 0; i < 2; i++) {
        float a = (v[i].x - mean) * r, b = (v[i].y - mean) * r;
        float c = (v[i].z - mean) * r, d = (v[i].w - mean) * r;
        size_t o = (size_t)row * (D_MODEL / 4) + threadIdx.x + i * 256;
        ((uint2*)oh)[o] = make_uint2(pack_h(a, b), pack_h(c, d));
    }
}

// ============================================================================
// 2) 4-stage cp.async fp16 GEMM (round-7 mainloop). CTA 128x128, 8 warps
//    (32x64 warp tiles), kstage=32, 2 CTAs/SM. bn0 = column-block offset.
// ============================================================================
#define GSTAGE 16384
#define GEMM_SMEM (4 * GSTAGE)   // 64 KB

template<bool QKV, bool ADD_RES>
__global__ __launch_bounds__(256, 2)
void tc_gemm7(const __half* __restrict__ Ah, int lda,
              const __half* __restrict__ Bh, int ldb,
              float* __restrict__ C, int ldc,
              const float* __restrict__ bias,
              const float* __restrict__ res,
              __half* __restrict__ Hh,
              __half* __restrict__ Qo, __half* __restrict__ Ko,
              __half* __restrict__ Vo,
              int K, int bn0) {
    extern __shared__ char gsm[];
    const uint32_t smb = smem_u32(gsm);

    const int tid = threadIdx.x;
    const int l = tid & 31, w = tid >> 5;
    const int wm = (w & 3) * 32;
    const int wn = (w >> 2) * 64;
    const int bm = blockIdx.x * 128, bn = (blockIdx.y + bn0) * 128;

    const int ar = tid >> 1;
    const int ac0 = (tid & 1) * 2;
    const int br = tid >> 3;
    const int bc0 = (tid & 7) * 2;

    float acc[2][8][4];
    #pragma unroll
    for (int mt = 0; mt < 2; mt++)
        #pragma unroll
        for (int nt = 0; nt < 8; nt++)
            #pragma unroll
            for (int e = 0; e < 4; e++) acc[mt][nt][e] = 0.f;

    const int nkb = K / 32;

    auto issue = [&](int stage, int k0) {
        uint32_t sb = smb + stage * GSTAGE;
        #pragma unroll
        for (int j = 0; j < 2; j++) {
            int c = ac0 + j;
            cp16(sb + ar * 64 + 16 * (c ^ ((ar >> 1) & 3)),
                 Ah + (size_t)(bm + ar) * lda + k0 + c * 8);
        }
        #pragma unroll
        for (int j = 0; j < 2; j++) {
            int c = bc0 + j;
            cp16(sb + 8192 + br * 256 + 16 * ((c & 8) | ((c ^ br) & 7)),
                 Bh + (size_t)(k0 + br) * ldb + bn + c * 8);
        }
    };

    issue(0, 0);  CP_COMMIT();
    issue(1, 32); CP_COMMIT();
    issue(2, 64); CP_COMMIT();

    for (int kb = 0; kb < nkb; kb++) {
        int rem = nkb - 1 - kb;
        if (rem >= 2)      { CP_WAIT2(); }
        else if (rem == 1) { CP_WAIT1(); }
        else               { CP_WAIT0(); }
        __syncthreads();
        if (kb + 3 < nkb) { issue((kb + 3) & 3, (kb + 3) * 32); CP_COMMIT(); }

        uint32_t sb = smb + (kb & 3) * GSTAGE;
        #pragma unroll
        for (int ks = 0; ks < 2; ks++) {
            uint32_t A[2][4];
            #pragma unroll
            for (int mt = 0; mt < 2; mt++) {
                int r = wm + mt * 16 + (l & 15);
                int c = ks * 2 + (l >> 4);
                ldsm_x4(A[mt][0], A[mt][1], A[mt][2], A[mt][3],
                        sb + r * 64 + 16 * (c ^ ((r >> 1) & 3)));
            }
            uint32_t B[4][4];
            #pragma unroll
            for (int p = 0; p < 4; p++) {
                int g = (w >> 2) * 4 + p;
                int kk = ks * 16 + (l & 7) + ((l >> 3) & 1) * 8;
                int c = 2 * g + ((l >> 4) & 1);
                ldsm_x4t(B[p][0], B[p][1], B[p][2], B[p][3],
                         sb + 8192 + kk * 256 + 16 * ((c & 8) | ((c ^ kk) & 7)));
            }
            #pragma unroll
            for (int p = 0; p < 4; p++)
                #pragma unroll
                for (int mt = 0; mt < 2; mt++) {
                    mma_f16(acc[mt][p * 2],     A[mt][0], A[mt][1], A[mt][2], A[mt][3], B[p][0], B[p][1]);
                    mma_f16(acc[mt][p * 2 + 1], A[mt][0], A[mt][1], A[mt][2], A[mt][3], B[p][2], B[p][3]);
                }
        }
    }

    // ---- epilogue ----
    if (QKV && bn >= QKV3) {
        // hidden block: fused GELU -> fp16
        #pragma unroll
        for (int mt = 0; mt < 2; mt++) {
            int row0 = bm + wm + mt * 16 + (l >> 2);
            #pragma unroll
            for (int nt = 0; nt < 8; nt++) {
                int col = bn + wn + nt * 8 + (l & 3) * 2;
                int hcol = col - QKV3;
                float b0 = bias[col], b1 = bias[col + 1];
                float* d = acc[mt][nt];
                *(uint32_t*)(Hh + (size_t)row0 * HIDDEN + hcol) =
                    pack_h(gelu_f(d[0] + b0), gelu_f(d[1] + b1));
                *(uint32_t*)(Hh + (size_t)(row0 + 8) * HIDDEN + hcol) =
                    pack_h(gelu_f(d[2] + b0), gelu_f(d[3] + b1));
            }
        }
    } else if (QKV) {
        // q/k/v block: this CTA column block == exactly one head
        const int seg = bn >> 11;            // 0=q, 1=k, 2=v
        const int hd  = (bn >> 7) & 15;      // head index
        __half* dst = (seg == 0) ? Qo : (seg == 1) ? Ko : Vo;

        #pragma unroll
        for (int mt = 0; mt < 2; mt++)
            #pragma unroll
            for (int nt = 0; nt < 8; nt++) {
                int col = bn + wn + nt * 8 + (l & 3) * 2;
                float b0 = bias[col], b1 = bias[col + 1];
                float* d = acc[mt][nt];
                d[0] += b0; d[1] += b1; d[2] += b0; d[3] += b1;
            }

        float mean_[4], rr_[4];
        if (seg < 2) {
            float ps[4] = {0.f, 0.f, 0.f, 0.f}, pq[4] = {0.f, 0.f, 0.f, 0.f};
            #pragma unroll
            for (int mt = 0; mt < 2; mt++)
                #pragma unroll
                for (int nt = 0; nt < 8; nt++) {
                    float* d = acc[mt][nt];
                    ps[mt * 2]     += d[0] + d[1];
                    pq[mt * 2]     += d[0] * d[0] + d[1] * d[1];
                    ps[mt * 2 + 1] += d[2] + d[3];
                    pq[mt * 2 + 1] += d[2] * d[2] + d[3] * d[3];
                }
            #pragma unroll
            for (int o = 1; o < 4; o <<= 1)
                #pragma unroll
                for (int i = 0; i < 4; i++) {
                    ps[i] += __shfl_xor_sync(0xffffffffu, ps[i], o);
                    pq[i] += __shfl_xor_sync(0xffffffffu, pq[i], o);
                }
            float* red = (float*)gsm;
            __syncthreads();
            if ((l & 3) == 0) {
                #pragma unroll
                for (int i = 0; i < 4; i++) {
                    int r = wm + (i >> 1) * 16 + (i & 1) * 8 + (l >> 2);
                    red[(w >> 2) * 128 + r]       = ps[i];
                    red[256 + (w >> 2) * 128 + r] = pq[i];
                }
            }
            __syncthreads();
            #pragma unroll
            for (int i = 0; i < 4; i++) {
                int r = wm + (i >> 1) * 16 + (i & 1) * 8 + (l >> 2);
                float tot = red[r] + red[128 + r];
                float sqt = red[256 + r] + red[256 + 128 + r];
                float mean = tot * (1.f / HEAD);
                float var  = sqt * (1.f / HEAD) - mean * mean;
                float rr = rsqrtf(var + 1e-5f);
                // q: fold 1/sqrt(HEAD) AND log2(e)  (softmax works in base-2)
                if (seg == 0) rr *= 0.08838834764831845f * 1.4426950408889634f;
                mean_[i] = mean; rr_[i] = rr;
            }
        } else {
            #pragma unroll
            for (int i = 0; i < 4; i++) { mean_[i] = 0.f; rr_[i] = 1.f; }
        }

        #pragma unroll
        for (int mt = 0; mt < 2; mt++) {
            #pragma unroll
            for (int half = 0; half < 2; half++) {
                int i = mt * 2 + half;
                int r = wm + mt * 16 + half * 8 + (l >> 2);
                int token = bm + r;
                int b = token >> 11, tt = token & 2047;
                __half* rowp = dst + ((((size_t)b * 16 + hd) * 2048 + tt) * 128);
                #pragma unroll
                for (int nt = 0; nt < 8; nt++) {
                    int dcol = wn + nt * 8 + (l & 3) * 2;
                    float* d = acc[mt][nt];
                    float v0 = (d[half * 2]     - mean_[i]) * rr_[i];
                    float v1 = (d[half * 2 + 1] - mean_[i]) * rr_[i];
                    *(uint32_t*)(rowp + dcol) = pack_h(v0, v1);
                }
            }
        }
    } else {
        #pragma unroll
        for (int mt = 0; mt < 2; mt++) {
            int row0 = bm + wm + mt * 16 + (l >> 2);
            #pragma unroll
            for (int nt = 0; nt < 8; nt++) {
                int col = bn + wn + nt * 8 + (l & 3) * 2;
                float b0 = bias[col], b1 = bias[col + 1];
                float* d = acc[mt][nt];
                float2 o0 = make_float2(d[0] + b0, d[1] + b1);
                float2 o1 = make_float2(d[2] + b0, d[3] + b1);
                if (ADD_RES) {
                    float2 r0 = *(const float2*)(res + (size_t)row0 * ldc + col);
                    float2 r1 = *(const float2*)(res + (size_t)(row0 + 8) * ldc + col);
                    o0.x += r0.x; o0.y += r0.y;
                    o1.x += r1.x; o1.y += r1.y;
                }
                *(float2*)(C + (size_t)row0 * ldc + col) = o0;
                *(float2*)(C + (size_t)(row0 + 8) * ldc + col) = o1;
            }
        }
    }
}

// ============================================================================
// 3) flash v7: log2-domain softmax with ex2.approx.f16x2 (2 exps / MUFU op),
//    qt-paired work balance. grid (8, 32); CTA does qt=bx, then 15-bx.
// ============================================================================
#define FLASH_SMEM 98304   // Q 32KB + 2 stages x (K 16KB + V 16KB)

__global__ __launch_bounds__(256, 2)
void flash7_kernel(const __half* __restrict__ qh, const __half* __restrict__ kh,
                   const __half* __restrict__ vh, float* __restrict__ attn) {
    extern __shared__ char fsm[];
    const uint32_t sb = smem_u32(fsm);
    const int tid = threadIdx.x;
    const int l = tid & 31, w = tid >> 5;
    const int bx = blockIdx.x;
    const int bh = blockIdx.y;
    const size_t hbase = (size_t)bh * 2048 * 128;

    auto issue_kv = [&](int stage, int kt) {
        uint32_t stb = sb + 32768 + stage * 32768;
        int r = tid >> 2, q4 = tid & 3;
        const __half* pk = kh + hbase + (size_t)(kt * 64 + r) * 128;
        const __half* pv = vh + hbase + (size_t)(kt * 64 + r) * 128;
        #pragma unroll
        for (int j = 0; j < 4; j++) {
            int c = q4 * 4 + j;
            uint32_t sw = r * 256 + 16 * ((c & 8) | ((c ^ r) & 7));
            cp16(stb + sw,         pk + c * 8);
            cp16(stb + 16384 + sw, pv + c * 8);
        }
    };

    #pragma unroll 1
    for (int pair = 0; pair < 2; pair++) {
        const int qt = pair ? (15 - bx) : bx;

        if (pair) __syncthreads();

        // ---- issue Q (128 rows x 256B) ----
        {
            int row = tid >> 1, half = tid & 1;
            const __half* sq = qh + hbase + (size_t)(qt * 128 + row) * 128;
            #pragma unroll
            for (int j = 0; j < 8; j++) {
                int c = half * 8 + j;
                cp16(sb + row * 256 + 16 * ((c & 8) | ((c ^ row) & 7)), sq + c * 8);
            }
        }
        CP_COMMIT();
        issue_kv(0, 0);
        CP_COMMIT();

        float O_[16][4];
        #pragma unroll
        for (int t = 0; t < 16; t++)
            #pragma unroll
            for (int e = 0; e < 4; e++) O_[t][e] = 0.f;
        float M0 = -INFINITY, M1 = -INFINITY, L0 = 0.f, L1 = 0.f;
        const int ktmax = 2 * qt + 1;

        for (int kt = 0; kt <= ktmax; kt++) {
            CP_WAIT0();
            __syncthreads();
            if (kt < ktmax) { issue_kv((kt + 1) & 1, kt + 1); CP_COMMIT(); }

            uint32_t stb = sb + 32768 + (kt & 1) * 32768;

            // ---- S = Q K^T (S is in log2 domain: log2e folded into q) ----
            float s_[8][4];
            #pragma unroll
            for (int t = 0; t < 8; t++)
                #pragma unroll
                for (int e = 0; e < 4; e++) s_[t][e] = 0.f;

            #pragma unroll
            for (int ks = 0; ks < 8; ks++) {
                int qr = w * 16 + (l & 15);
                int qc = ks * 2 + (l >> 4);
                uint32_t q0, q1, q2, q3;
                ldsm_x4(q0, q1, q2, q3, sb + qr * 256 + 16 * ((qc & 8) | ((qc ^ qr) & 7)));
                #pragma unroll
                for (int g = 0; g < 4; g++) {
                    int kr = g * 16 + (l & 7) + ((l >> 4) & 1) * 8;
                    int kc = ks * 2 + ((l >> 3) & 1);
                    uint32_t b0, b1, b2, b3;
                    ldsm_x4(b0, b1, b2, b3, stb + kr * 256 + 16 * ((kc & 8) | ((kc ^ kr) & 7)));
                    mma_f16(s_[2 * g],     q0, q1, q2, q3, b0, b1);
                    mma_f16(s_[2 * g + 1], q0, q1, q2, q3, b2, b3);
                }
            }

            if (kt >= 2 * qt) {
                int qr0 = qt * 128 + w * 16 + (l >> 2);
                int qr1 = qr0 + 8;
                #pragma unroll
                for (int t = 0; t < 8; t++) {
                    int kc = kt * 64 + t * 8 + (l & 3) * 2;
                    if (kc     > qr0) s_[t][0] = -INFINITY;
                    if (kc + 1 > qr0) s_[t][1] = -INFINITY;
                    if (kc     > qr1) s_[t][2] = -INFINITY;
                    if (kc + 1 > qr1) s_[t][3] = -INFINITY;
                }
            }

            // ---- online softmax (base-2) ----
            float m0 = -INFINITY, m1 = -INFINITY;
            #pragma unroll
            for (int t = 0; t < 8; t++) {
                m0 = fmaxf(m0, fmaxf(s_[t][0], s_[t][1]));
                m1 = fmaxf(m1, fmaxf(s_[t][2], s_[t][3]));
            }
            #pragma unroll
            for (int o = 1; o < 4; o <<= 1) {
                m0 = fmaxf(m0, __shfl_xor_sync(0xffffffffu, m0, o));
                m1 = fmaxf(m1, __shfl_xor_sync(0xffffffffu, m1, o));
            }
            float nm0 = fmaxf(M0, m0), nm1 = fmaxf(M1, m1);
            float corr0 = ex2f(M0 - nm0), corr1 = ex2f(M1 - nm1);
            M0 = nm0; M1 = nm1;

            // P = 2^(s - m) as fp16 pairs (one MUFU per pair); L in fp32
            uint32_t P[8][2];
            float ps0 = 0.f, ps1 = 0.f;
            #pragma unroll
            for (int t = 0; t < 8; t++) {
                uint32_t p0 = ex2_f16x2(s_[t][0] - nm0, s_[t][1] - nm0);
                uint32_t p1 = ex2_f16x2(s_[t][2] - nm1, s_[t][3] - nm1);
                P[t][0] = p0; P[t][1] = p1;
                float2 f0 = __half22float2(*(__half2*)&p0);
                float2 f1 = __half22float2(*(__half2*)&p1);
                ps0 += f0.x + f0.y;
                ps1 += f1.x + f1.y;
            }
            #pragma unroll
            for (int o = 1; o < 4; o <<= 1) {
                ps0 += __shfl_xor_sync(0xffffffffu, ps0, o);
                ps1 += __shfl_xor_sync(0xffffffffu, ps1, o);
            }
            L0 = L0 * corr0 + ps0;
            L1 = L1 * corr1 + ps1;
            #pragma unroll
            for (int t = 0; t < 16; t++) {
                O_[t][0] *= corr0; O_[t][1] *= corr0;
                O_[t][2] *= corr1; O_[t][3] *= corr1;
            }

            // ---- O += P V ----
            #pragma unroll
            for (int s8 = 0; s8 < 4; s8++) {
                uint32_t ph[4];
                ph[0] = P[2 * s8][0];
                ph[1] = P[2 * s8][1];
                ph[2] = P[2 * s8 + 1][0];
                ph[3] = P[2 * s8 + 1][1];
                #pragma unroll
                for (int g = 0; g < 8; g++) {
                    int vr = s8 * 16 + (l & 7) + ((l >> 3) & 1) * 8;
                    int vc = 2 * g + ((l >> 4) & 1);
                    uint32_t v0, v1, v2, v3;
                    ldsm_x4t(v0, v1, v2, v3,
                             stb + 16384 + vr * 256 + 16 * ((vc & 8) | ((vc ^ vr) & 7)));
                    mma_f16(O_[2 * g],     ph[0], ph[1], ph[2], ph[3], v0, v1);
                    mma_f16(O_[2 * g + 1], ph[0], ph[1], ph[2], ph[3], v2, v3);
                }
            }
        }

        // ---- epilogue: attn = O / L ----
        int b = bh >> 4, h = bh & 15;
        float inv0 = 1.f / L0, inv1 = 1.f / L1;
        int token = qt * 128 + w * 16 + (l >> 2);
        float* row0p = attn + (size_t)(b * TT + token) * D_MODEL + h * HEAD;
        float* row1p = row0p + (size_t)8 * D_MODEL;
        #pragma unroll
        for (int t = 0; t < 16; t++) {
            int col = t * 8 + (l & 3) * 2;
            *(float2*)(row0p + col) = make_float2(O_[t][0] * inv0, O_[t][1] * inv0);
            *(float2*)(row1p + col) = make_float2(O_[t][2] * inv1, O_[t][3] * inv1);
        }
    }
}

// ---------------- 4) out += attn --------------------------------------------
__global__ void attn_add_kernel(float* __restrict__ out, const float* __restrict__ attn) {
    int idx = blockIdx.x * blockDim.x + threadIdx.x;
    float4 o = ((float4*)out)[idx];
    float4 a = ((const float4*)attn)[idx];
    o.x += a.x; o.y += a.y; o.z += a.z; o.w += a.w;
    ((float4*)out)[idx] = o;
}

// ---------------- launch ----------------------------------------------------
extern "C" void kernel_launch(void* const* d_in, const int* in_sizes, int n_in,
                              void* d_out, int out_size) {
    const float* inputs = (const float*)d_in[0];
    const float* W_qkv  = (const float*)d_in[1];
    const float* b_qkv  = (const float*)d_in[2];
    const float* W_mlp  = (const float*)d_in[3];
    const float* b_mlp  = (const float*)d_in[4];
    float* out = (float*)d_out;

    void *pa, *px, *pwq, *pwm, *ph, *pqo, *pko, *pvo;
    cudaGetSymbolAddress(&pa,  g_attn);
    cudaGetSymbolAddress(&px,  g_x);
    cudaGetSymbolAddress(&pwq, g_wq);
    cudaGetSymbolAddress(&pwm, g_wm);
    cudaGetSymbolAddress(&ph,  g_h);
    cudaGetSymbolAddress(&pqo, g_q);
    cudaGetSymbolAddress(&pko, g_k);
    cudaGetSymbolAddress(&pvo, g_v);
    float* gattn = (float*)pa;

    cudaFuncSetAttribute(tc_gemm7<true, false>,
                         cudaFuncAttributeMaxDynamicSharedMemorySize, GEMM_SMEM);
    cudaFuncSetAttribute(tc_gemm7<false, true>,
                         cudaFuncAttributeMaxDynamicSharedMemorySize, GEMM_SMEM);
    cudaFuncSetAttribute(flash7_kernel,
                         cudaFuncAttributeMaxDynamicSharedMemorySize, FLASH_SMEM);

    cudaStream_t s1;
    cudaStreamCreateWithFlags(&s1, cudaStreamNonBlocking);
    cudaEvent_t e0, e1;
    cudaEventCreateWithFlags(&e0, cudaEventDisableTiming);
    cudaEventCreateWithFlags(&e1, cudaEventDisableTiming);

    // ---- side stream: W_mlp convert (overlaps main-stream pre) ----
    convert_kernel<<<(HIDDEN * D_MODEL / 4) / 256, 256, 0, s1>>>(W_mlp, (__half*)pwm);

    // 0) convert W_qkv; 1) LN(inputs) -> fp16  (main)
    convert_kernel<<<(D_MODEL * QKV_OUT / 4) / 256, 256>>>(W_qkv, (__half*)pwq);
    ln_input_kernel<<<BT, 256>>>(inputs, (__half*)px);

    // 2) qkv-part GEMM solo (fused head-LN; q scaled by 1/sqrt(d)*log2e)
    tc_gemm7<true, false><<<dim3(BT / 128, QKV3 / 128), 256, GEMM_SMEM>>>(
        (__half*)px, D_MODEL, (__half*)pwq, QKV_OUT,
        nullptr, 0, b_qkv, nullptr, (__half*)ph,
        (__half*)pqo, (__half*)pko, (__half*)pvo, D_MODEL, 0);
    cudaEventRecord(e0, 0);

    // ---- s1: hidden-part GEMM (GELU->fp16) then MLP ----
    cudaStreamWaitEvent(s1, e0, 0);
    tc_gemm7<true, false><<<dim3(BT / 128, (QKV_OUT - QKV3) / 128), 256, GEMM_SMEM, s1>>>(
        (__half*)px, D_MODEL, (__half*)pwq, QKV_OUT,
        nullptr, 0, b_qkv, nullptr, (__half*)ph,
        nullptr, nullptr, nullptr, D_MODEL, QKV3 / 128);
    tc_gemm7<false, true><<<dim3(BT / 128, D_MODEL / 128), 256, GEMM_SMEM, s1>>>(
        (__half*)ph, HIDDEN, (__half*)pwm, D_MODEL,
        out, D_MODEL, b_mlp, inputs, nullptr,
        nullptr, nullptr, nullptr, HIDDEN, 0);
    cudaEventRecord(e1, s1);

    // ---- main: flash (overlaps hidden GEMM + MLP) ----
    flash7_kernel<<<dim3(8, BB * NUM_HEADS), 256, FLASH_SMEM>>>(
        (__half*)pqo, (__half*)pko, (__half*)pvo, gattn);

    // ---- join, then out += attn ----
    cudaStreamWaitEvent(0, e1, 0);
    attn_add_kernel<<<(BT * D_MODEL / 4) / 256, 256>>>(out, gattn);
}

// round 13
// speedup vs baseline: 1.0287x; 1.0287x over previous
#include <cuda_runtime.h>
#include <cuda_fp16.h>
#include <math.h>
#include <stdint.h>

#define D_MODEL   2048
#define NUM_HEADS 16
#define HEAD      128
#define FAN       4
#define QKV_OUT   (3 * D_MODEL + FAN * D_MODEL)   // 14336
#define HIDDEN    (FAN * D_MODEL)                 // 8192
#define BB        2
#define TT        2048
#define BT        (BB * TT)                       // 4096
#define QKV3      (3 * D_MODEL)                   // 6144

// ---------------- scratch (device globals) ---------------------------------
__device__ float  g_attn[(size_t)BT * D_MODEL];   // attention output scratch
__device__ __half g_x[(size_t)BT * D_MODEL];
__device__ __half g_wq[(size_t)D_MODEL * QKV_OUT];
__device__ __half g_wm[(size_t)HIDDEN * D_MODEL];
__device__ __half g_h[(size_t)BT * HIDDEN];
// head-major [b][h][t][d] q/k/v for flash
__device__ __half g_q[(size_t)BT * D_MODEL];
__device__ __half g_k[(size_t)BT * D_MODEL];
__device__ __half g_v[(size_t)BT * D_MODEL];

// ---------------- PTX helpers ----------------------------------------------
__device__ __forceinline__ uint32_t smem_u32(const void* p) {
    uint32_t a;
    asm("{ .reg .u64 t; cvta.to.shared.u64 t, %1; cvt.u32.u64 %0, t; }"
        : "=r"(a) : "l"(p));
    return a;
}
__device__ __forceinline__ void cp16(uint32_t dst, const void* src) {
    asm volatile("cp.async.cg.shared.global [%0], [%1], 16;" :: "r"(dst), "l"(src));
}
#define CP_COMMIT() asm volatile("cp.async.commit_group;")
#define CP_WAIT0()  asm volatile("cp.async.wait_group 0;")
#define CP_WAIT1()  asm volatile("cp.async.wait_group 1;")
#define CP_WAIT2()  asm volatile("cp.async.wait_group 2;")

__device__ __forceinline__ void ldsm_x4(uint32_t& r0, uint32_t& r1,
                                        uint32_t& r2, uint32_t& r3, uint32_t addr) {
    asm volatile("ldmatrix.sync.aligned.m8n8.x4.shared.b16 {%0,%1,%2,%3}, [%4];"
                 : "=r"(r0), "=r"(r1), "=r"(r2), "=r"(r3) : "r"(addr));
}
__device__ __forceinline__ void ldsm_x4t(uint32_t& r0, uint32_t& r1,
                                         uint32_t& r2, uint32_t& r3, uint32_t addr) {
    asm volatile("ldmatrix.sync.aligned.m8n8.x4.trans.shared.b16 {%0,%1,%2,%3}, [%4];"
                 : "=r"(r0), "=r"(r1), "=r"(r2), "=r"(r3) : "r"(addr));
}
__device__ __forceinline__ void mma_f16(float* d,
                                        uint32_t a0, uint32_t a1, uint32_t a2, uint32_t a3,
                                        uint32_t b0, uint32_t b1) {
    asm volatile(
        "mma.sync.aligned.m16n8k16.row.col.f32.f16.f16.f32 "
        "{%0,%1,%2,%3}, {%4,%5,%6,%7}, {%8,%9}, {%0,%1,%2,%3};"
        : "+f"(d[0]), "+f"(d[1]), "+f"(d[2]), "+f"(d[3])
        : "r"(a0), "r"(a1), "r"(a2), "r"(a3), "r"(b0), "r"(b1));
}
__device__ __forceinline__ uint32_t pack_h(float x, float y) {
    __half2 h = __float22half2_rn(make_float2(x, y));
    return *(uint32_t*)&h;
}
// two exps in one MUFU op (fp16x2, base-2)
__device__ __forceinline__ uint32_t ex2_f16x2(float a, float b) {
    uint32_t in = pack_h(a, b), out;
    asm("ex2.approx.f16x2 %0, %1;" : "=r"(out) : "r"(in));
    return out;
}
__device__ __forceinline__ float ex2f(float x) {
    float y; asm("ex2.approx.f32 %0, %1;" : "=f"(y) : "f"(x)); return y;
}
__device__ __forceinline__ float warp_sum(float v) {
    #pragma unroll
    for (int o = 16; o > 0; o >>= 1) v += __shfl_xor_sync(0xffffffffu, v, o);
    return v;
}
__device__ __forceinline__ float gelu_f(float x) {
    return 0.5f * x * (1.f + erff(x * 0.70710678118654752f));
}

// ---------------- 0) fp32 -> fp16 convert (weights) -------------------------
__global__ void convert_kernel(const float* __restrict__ in, __half* __restrict__ oh) {
    int idx = blockIdx.x * blockDim.x + threadIdx.x;
    float4 v = ((const float4*)in)[idx];
    ((uint2*)oh)[idx] = make_uint2(pack_h(v.x, v.y), pack_h(v.z, v.w));
}

// ---------------- 1) LayerNorm(inputs) -> fp16 ------------------------------
__global__ void ln_input_kernel(const float* __restrict__ in, __half* __restrict__ oh) {
    int row = blockIdx.x;
    const float4* src = (const float4*)(in + (size_t)row * D_MODEL);

    float4 v[2];
    float s = 0.f, sq = 0.f;
    #pragma unroll
    for (int i = 0; i < 2; i++) {
        v[i] = src[threadIdx.x + i * 256];
        s  += v[i].x + v[i].y + v[i].z + v[i].w;
        sq += v[i].x * v[i].x + v[i].y * v[i].y + v[i].z * v[i].z + v[i].w * v[i].w;
    }
    __shared__ float sh_s[8], sh_q[8];
    int lane = threadIdx.x & 31, wid = threadIdx.x >> 5;
    s = warp_sum(s); sq = warp_sum(sq);
    if (lane == 0) { sh_s[wid] = s; sh_q[wid] = sq; }
    __syncthreads();
    if (wid == 0) {
        float a = (lane < 8) ? sh_s[lane] : 0.f;
        float b = (lane < 8) ? sh_q[lane] : 0.f;
        a = warp_sum(a); b = warp_sum(b);
        if (lane == 0) { sh_s[0] = a; sh_q[0] = b; }
    }
    __syncthreads();
    float mean = sh_s[0] * (1.f / D_MODEL);
    float var  = sh_q[0] * (1.f / D_MODEL) - mean * mean;
    float r    = rsqrtf(var + 1e-5f);
    #pragma unroll
    for (int i = 0; i < 2; i++) {
        float a = (v[i].x - mean) * r, b = (v[i].y - mean) * r;
        float c = (v[i].z - mean) * r, d = (v[i].w - mean) * r;
        size_t o = (size_t)row * (D_MODEL / 4) + threadIdx.x + i * 256;
        ((uint2*)oh)[o] = make_uint2(pack_h(a, b), pack_h(c, d));
    }
}

// ============================================================================
// 2) 4-stage cp.async fp16 GEMM (round-7 mainloop). CTA 128x128, 8 warps
//    (32x64 warp tiles), kstage=32, 2 CTAs/SM. bn0 = column-block offset.
// ============================================================================
#define GSTAGE 16384
#define GEMM_SMEM (4 * GSTAGE)   // 64 KB

template<bool QKV, bool ADD_RES>
__global__ __launch_bounds__(256, 2)
void tc_gemm7(const __half* __restrict__ Ah, int lda,
              const __half* __restrict__ Bh, int ldb,
              float* __restrict__ C, int ldc,
              const float* __restrict__ bias,
              const float* __restrict__ res,
              __half* __restrict__ Hh,
              __half* __restrict__ Qo, __half* __restrict__ Ko,
              __half* __restrict__ Vo,
              int K, int bn0) {
    extern __shared__ char gsm[];
    const uint32_t smb = smem_u32(gsm);

    const int tid = threadIdx.x;
    const int l = tid & 31, w = tid >> 5;
    const int wm = (w & 3) * 32;
    const int wn = (w >> 2) * 64;
    const int bm = blockIdx.x * 128, bn = (blockIdx.y + bn0) * 128;

    const int ar = tid >> 1;
    const int ac0 = (tid & 1) * 2;
    const int br = tid >> 3;
    const int bc0 = (tid & 7) * 2;

    float acc[2][8][4];
    #pragma unroll
    for (int mt = 0; mt < 2; mt++)
        #pragma unroll
        for (int nt = 0; nt < 8; nt++)
            #pragma unroll
            for (int e = 0; e < 4; e++) acc[mt][nt][e] = 0.f;

    const int nkb = K / 32;

    auto issue = [&](int stage, int k0) {
        uint32_t sb = smb + stage * GSTAGE;
        #pragma unroll
        for (int j = 0; j < 2; j++) {
            int c = ac0 + j;
            cp16(sb + ar * 64 + 16 * (c ^ ((ar >> 1) & 3)),
                 Ah + (size_t)(bm + ar) * lda + k0 + c * 8);
        }
        #pragma unroll
        for (int j = 0; j < 2; j++) {
            int c = bc0 + j;
            cp16(sb + 8192 + br * 256 + 16 * ((c & 8) | ((c ^ br) & 7)),
                 Bh + (size_t)(k0 + br) * ldb + bn + c * 8);
        }
    };

    issue(0, 0);  CP_COMMIT();
    issue(1, 32); CP_COMMIT();
    issue(2, 64); CP_COMMIT();

    for (int kb = 0; kb < nkb; kb++) {
        int rem = nkb - 1 - kb;
        if (rem >= 2)      { CP_WAIT2(); }
        else if (rem == 1) { CP_WAIT1(); }
        else               { CP_WAIT0(); }
        __syncthreads();
        if (kb + 3 < nkb) { issue((kb + 3) & 3, (kb + 3) * 32); CP_COMMIT(); }

        uint32_t sb = smb + (kb & 3) * GSTAGE;
        #pragma unroll
        for (int ks = 0; ks < 2; ks++) {
            uint32_t A[2][4];
            #pragma unroll
            for (int mt = 0; mt < 2; mt++) {
                int r = wm + mt * 16 + (l & 15);
                int c = ks * 2 + (l >> 4);
                ldsm_x4(A[mt][0], A[mt][1], A[mt][2], A[mt][3],
                        sb + r * 64 + 16 * (c ^ ((r >> 1) & 3)));
            }
            uint32_t B[4][4];
            #pragma unroll
            for (int p = 0; p < 4; p++) {
                int g = (w >> 2) * 4 + p;
                int kk = ks * 16 + (l & 7) + ((l >> 3) & 1) * 8;
                int c = 2 * g + ((l >> 4) & 1);
                ldsm_x4t(B[p][0], B[p][1], B[p][2], B[p][3],
                         sb + 8192 + kk * 256 + 16 * ((c & 8) | ((c ^ kk) & 7)));
            }
            #pragma unroll
            for (int p = 0; p < 4; p++)
                #pragma unroll
                for (int mt = 0; mt < 2; mt++) {
                    mma_f16(acc[mt][p * 2],     A[mt][0], A[mt][1], A[mt][2], A[mt][3], B[p][0], B[p][1]);
                    mma_f16(acc[mt][p * 2 + 1], A[mt][0], A[mt][1], A[mt][2], A[mt][3], B[p][2], B[p][3]);
                }
        }
    }

    // ---- epilogue ----
    if (QKV && bn >= QKV3) {
        // hidden block: fused GELU -> fp16
        #pragma unroll
        for (int mt = 0; mt < 2; mt++) {
            int row0 = bm + wm + mt * 16 + (l >> 2);
            #pragma unroll
            for (int nt = 0; nt < 8; nt++) {
                int col = bn + wn + nt * 8 + (l & 3) * 2;
                int hcol = col - QKV3;
                float b0 = bias[col], b1 = bias[col + 1];
                float* d = acc[mt][nt];
                *(uint32_t*)(Hh + (size_t)row0 * HIDDEN + hcol) =
                    pack_h(gelu_f(d[0] + b0), gelu_f(d[1] + b1));
                *(uint32_t*)(Hh + (size_t)(row0 + 8) * HIDDEN + hcol) =
                    pack_h(gelu_f(d[2] + b0), gelu_f(d[3] + b1));
            }
        }
    } else if (QKV) {
        // q/k/v block: this CTA column block == exactly one head
        const int seg = bn >> 11;            // 0=q, 1=k, 2=v
        const int hd  = (bn >> 7) & 15;      // head index
        __half* dst = (seg == 0) ? Qo : (seg == 1) ? Ko : Vo;

        #pragma unroll
        for (int mt = 0; mt < 2; mt++)
            #pragma unroll
            for (int nt = 0; nt < 8; nt++) {
                int col = bn + wn + nt * 8 + (l & 3) * 2;
                float b0 = bias[col], b1 = bias[col + 1];
                float* d = acc[mt][nt];
                d[0] += b0; d[1] += b1; d[2] += b0; d[3] += b1;
            }

        float mean_[4], rr_[4];
        if (seg < 2) {
            float ps[4] = {0.f, 0.f, 0.f, 0.f}, pq[4] = {0.f, 0.f, 0.f, 0.f};
            #pragma unroll
            for (int mt = 0; mt < 2; mt++)
                #pragma unroll
                for (int nt = 0; nt < 8; nt++) {
                    float* d = acc[mt][nt];
                    ps[mt * 2]     += d[0] + d[1];
                    pq[mt * 2]     += d[0] * d[0] + d[1] * d[1];
                    ps[mt * 2 + 1] += d[2] + d[3];
                    pq[mt * 2 + 1] += d[2] * d[2] + d[3] * d[3];
                }
            #pragma unroll
            for (int o = 1; o < 4; o <<= 1)
                #pragma unroll
                for (int i = 0; i < 4; i++) {
                    ps[i] += __shfl_xor_sync(0xffffffffu, ps[i], o);
                    pq[i] += __shfl_xor_sync(0xffffffffu, pq[i], o);
                }
            float* red = (float*)gsm;
            __syncthreads();
            if ((l & 3) == 0) {
                #pragma unroll
                for (int i = 0; i < 4; i++) {
                    int r = wm + (i >> 1) * 16 + (i & 1) * 8 + (l >> 2);
                    red[(w >> 2) * 128 + r]       = ps[i];
                    red[256 + (w >> 2) * 128 + r] = pq[i];
                }
            }
            __syncthreads();
            #pragma unroll
            for (int i = 0; i < 4; i++) {
                int r = wm + (i >> 1) * 16 + (i & 1) * 8 + (l >> 2);
                float tot = red[r] + red[128 + r];
                float sqt = red[256 + r] + red[256 + 128 + r];
                float mean = tot * (1.f / HEAD);
                float var  = sqt * (1.f / HEAD) - mean * mean;
                float rr = rsqrtf(var + 1e-5f);
                // q: fold 1/sqrt(HEAD) AND log2(e)  (softmax works in base-2)
                if (seg == 0) rr *= 0.08838834764831845f * 1.4426950408889634f;
                mean_[i] = mean; rr_[i] = rr;
            }
        } else {
            #pragma unroll
            for (int i = 0; i < 4; i++) { mean_[i] = 0.f; rr_[i] = 1.f; }
        }

        #pragma unroll
        for (int mt = 0; mt < 2; mt++) {
            #pragma unroll
            for (int half = 0; half < 2; half++) {
                int i = mt * 2 + half;
                int r = wm + mt * 16 + half * 8 + (l >> 2);
                int token = bm + r;
                int b = token >> 11, tt = token & 2047;
                __half* rowp = dst + ((((size_t)b * 16 + hd) * 2048 + tt) * 128);
                #pragma unroll
                for (int nt = 0; nt < 8; nt++) {
                    int dcol = wn + nt * 8 + (l & 3) * 2;
                    float* d = acc[mt][nt];
                    float v0 = (d[half * 2]     - mean_[i]) * rr_[i];
                    float v1 = (d[half * 2 + 1] - mean_[i]) * rr_[i];
                    *(uint32_t*)(rowp + dcol) = pack_h(v0, v1);
                }
            }
        }
    } else {
        #pragma unroll
        for (int mt = 0; mt < 2; mt++) {
            int row0 = bm + wm + mt * 16 + (l >> 2);
            #pragma unroll
            for (int nt = 0; nt < 8; nt++) {
                int col = bn + wn + nt * 8 + (l & 3) * 2;
                float b0 = bias[col], b1 = bias[col + 1];
                float* d = acc[mt][nt];
                float2 o0 = make_float2(d[0] + b0, d[1] + b1);
                float2 o1 = make_float2(d[2] + b0, d[3] + b1);
                if (ADD_RES) {
                    float2 r0 = *(const float2*)(res + (size_t)row0 * ldc + col);
                    float2 r1 = *(const float2*)(res + (size_t)(row0 + 8) * ldc + col);
                    o0.x += r0.x; o0.y += r0.y;
                    o1.x += r1.x; o1.y += r1.y;
                }
                *(float2*)(C + (size_t)row0 * ldc + col) = o0;
                *(float2*)(C + (size_t)(row0 + 8) * ldc + col) = o1;
            }
        }
    }
}

// ============================================================================
// 3) flash v7: log2-domain softmax with ex2.approx.f16x2 (2 exps / MUFU op),
//    qt-paired work balance. grid (8, 32); CTA does qt=bx, then 15-bx.
// ============================================================================
#define FLASH_SMEM 98304   // Q 32KB + 2 stages x (K 16KB + V 16KB)

__global__ __launch_bounds__(256, 2)
void flash7_kernel(const __half* __restrict__ qh, const __half* __restrict__ kh,
                   const __half* __restrict__ vh, float* __restrict__ attn) {
    extern __shared__ char fsm[];
    const uint32_t sb = smem_u32(fsm);
    const int tid = threadIdx.x;
    const int l = tid & 31, w = tid >> 5;
    const int bx = blockIdx.x;
    const int bh = blockIdx.y;
    const size_t hbase = (size_t)bh * 2048 * 128;

    auto issue_kv = [&](int stage, int kt) {
        uint32_t stb = sb + 32768 + stage * 32768;
        int r = tid >> 2, q4 = tid & 3;
        const __half* pk = kh + hbase + (size_t)(kt * 64 + r) * 128;
        const __half* pv = vh + hbase + (size_t)(kt * 64 + r) * 128;
        #pragma unroll
        for (int j = 0; j < 4; j++) {
            int c = q4 * 4 + j;
            uint32_t sw = r * 256 + 16 * ((c & 8) | ((c ^ r) & 7));
            cp16(stb + sw,         pk + c * 8);
            cp16(stb + 16384 + sw, pv + c * 8);
        }
    };

    #pragma unroll 1
    for (int pair = 0; pair < 2; pair++) {
        const int qt = pair ? (15 - bx) : bx;

        if (pair) __syncthreads();

        // ---- issue Q (128 rows x 256B) ----
        {
            int row = tid >> 1, half = tid & 1;
            const __half* sq = qh + hbase + (size_t)(qt * 128 + row) * 128;
            #pragma unroll
            for (int j = 0; j < 8; j++) {
                int c = half * 8 + j;
                cp16(sb + row * 256 + 16 * ((c & 8) | ((c ^ row) & 7)), sq + c * 8);
            }
        }
        CP_COMMIT();
        issue_kv(0, 0);
        CP_COMMIT();

        float O_[16][4];
        #pragma unroll
        for (int t = 0; t < 16; t++)
            #pragma unroll
            for (int e = 0; e < 4; e++) O_[t][e] = 0.f;
        float M0 = -INFINITY, M1 = -INFINITY, L0 = 0.f, L1 = 0.f;
        const int ktmax = 2 * qt + 1;

        for (int kt = 0; kt <= ktmax; kt++) {
            CP_WAIT0();
            __syncthreads();
            if (kt < ktmax) { issue_kv((kt + 1) & 1, kt + 1); CP_COMMIT(); }

            uint32_t stb = sb + 32768 + (kt & 1) * 32768;

            // ---- S = Q K^T (S in log2 domain: log2e folded into q) ----
            float s_[8][4];
            #pragma unroll
            for (int t = 0; t < 8; t++)
                #pragma unroll
                for (int e = 0; e < 4; e++) s_[t][e] = 0.f;

            #pragma unroll
            for (int ks = 0; ks < 8; ks++) {
                int qr = w * 16 + (l & 15);
                int qc = ks * 2 + (l >> 4);
                uint32_t q0, q1, q2, q3;
                ldsm_x4(q0, q1, q2, q3, sb + qr * 256 + 16 * ((qc & 8) | ((qc ^ qr) & 7)));
                #pragma unroll
                for (int g = 0; g < 4; g++) {
                    int kr = g * 16 + (l & 7) + ((l >> 4) & 1) * 8;
                    int kc = ks * 2 + ((l >> 3) & 1);
                    uint32_t b0, b1, b2, b3;
                    ldsm_x4(b0, b1, b2, b3, stb + kr * 256 + 16 * ((kc & 8) | ((kc ^ kr) & 7)));
                    mma_f16(s_[2 * g],     q0, q1, q2, q3, b0, b1);
                    mma_f16(s_[2 * g + 1], q0, q1, q2, q3, b2, b3);
                }
            }

            if (kt >= 2 * qt) {
                int qr0 = qt * 128 + w * 16 + (l >> 2);
                int qr1 = qr0 + 8;
                #pragma unroll
                for (int t = 0; t < 8; t++) {
                    int kc = kt * 64 + t * 8 + (l & 3) * 2;
                    if (kc     > qr0) s_[t][0] = -INFINITY;
                    if (kc + 1 > qr0) s_[t][1] = -INFINITY;
                    if (kc     > qr1) s_[t][2] = -INFINITY;
                    if (kc + 1 > qr1) s_[t][3] = -INFINITY;
                }
            }

            // ---- online softmax (base-2) ----
            float m0 = -INFINITY, m1 = -INFINITY;
            #pragma unroll
            for (int t = 0; t < 8; t++) {
                m0 = fmaxf(m0, fmaxf(s_[t][0], s_[t][1]));
                m1 = fmaxf(m1, fmaxf(s_[t][2], s_[t][3]));
            }
            #pragma unroll
            for (int o = 1; o < 4; o <<= 1) {
                m0 = fmaxf(m0, __shfl_xor_sync(0xffffffffu, m0, o));
                m1 = fmaxf(m1, __shfl_xor_sync(0xffffffffu, m1, o));
            }
            float nm0 = fmaxf(M0, m0), nm1 = fmaxf(M1, m1);
            float corr0 = ex2f(M0 - nm0), corr1 = ex2f(M1 - nm1);
            M0 = nm0; M1 = nm1;

            // P = 2^(s - m) as fp16 pairs (one MUFU per pair); L in fp32
            uint32_t P[8][2];
            float ps0 = 0.f, ps1 = 0.f;
            #pragma unroll
            for (int t = 0; t < 8; t++) {
                uint32_t p0 = ex2_f16x2(s_[t][0] - nm0, s_[t][1] - nm0);
                uint32_t p1 = ex2_f16x2(s_[t][2] - nm1, s_[t][3] - nm1);
                P[t][0] = p0; P[t][1] = p1;
                float2 f0 = __half22float2(*(__half2*)&p0);
                float2 f1 = __half22float2(*(__half2*)&p1);
                ps0 += f0.x + f0.y;
                ps1 += f1.x + f1.y;
            }
            #pragma unroll
            for (int o = 1; o < 4; o <<= 1) {
                ps0 += __shfl_xor_sync(0xffffffffu, ps0, o);
                ps1 += __shfl_xor_sync(0xffffffffu, ps1, o);
            }
            L0 = L0 * corr0 + ps0;
            L1 = L1 * corr1 + ps1;
            #pragma unroll
            for (int t = 0; t < 16; t++) {
                O_[t][0] *= corr0; O_[t][1] *= corr0;
                O_[t][2] *= corr1; O_[t][3] *= corr1;
            }

            // ---- O += P V ----
            #pragma unroll
            for (int s8 = 0; s8 < 4; s8++) {
                uint32_t ph[4];
                ph[0] = P[2 * s8][0];
                ph[1] = P[2 * s8][1];
                ph[2] = P[2 * s8 + 1][0];
                ph[3] = P[2 * s8 + 1][1];
                #pragma unroll
                for (int g = 0; g < 8; g++) {
                    int vr = s8 * 16 + (l & 7) + ((l >> 3) & 1) * 8;
                    int vc = 2 * g + ((l >> 4) & 1);
                    uint32_t v0, v1, v2, v3;
                    ldsm_x4t(v0, v1, v2, v3,
                             stb + 16384 + vr * 256 + 16 * ((vc & 8) | ((vc ^ vr) & 7)));
                    mma_f16(O_[2 * g],     ph[0], ph[1], ph[2], ph[3], v0, v1);
                    mma_f16(O_[2 * g + 1], ph[0], ph[1], ph[2], ph[3], v2, v3);
                }
            }
        }

        // ---- epilogue: attn = O / L ----
        int b = bh >> 4, h = bh & 15;
        float inv0 = 1.f / L0, inv1 = 1.f / L1;
        int token = qt * 128 + w * 16 + (l >> 2);
        float* row0p = attn + (size_t)(b * TT + token) * D_MODEL + h * HEAD;
        float* row1p = row0p + (size_t)8 * D_MODEL;
        #pragma unroll
        for (int t = 0; t < 16; t++) {
            int col = t * 8 + (l & 3) * 2;
            *(float2*)(row0p + col) = make_float2(O_[t][0] * inv0, O_[t][1] * inv0);
            *(float2*)(row1p + col) = make_float2(O_[t][2] * inv1, O_[t][3] * inv1);
        }
    }
}

// ---------------- 4) out += attn --------------------------------------------
__global__ void attn_add_kernel(float* __restrict__ out, const float* __restrict__ attn) {
    int idx = blockIdx.x * blockDim.x + threadIdx.x;
    float4 o = ((float4*)out)[idx];
    float4 a = ((const float4*)attn)[idx];
    o.x += a.x; o.y += a.y; o.z += a.z; o.w += a.w;
    ((float4*)out)[idx] = o;
}

// ---------------- launch (round-11 schedule) --------------------------------
extern "C" void kernel_launch(void* const* d_in, const int* in_sizes, int n_in,
                              void* d_out, int out_size) {
    const float* inputs = (const float*)d_in[0];
    const float* W_qkv  = (const float*)d_in[1];
    const float* b_qkv  = (const float*)d_in[2];
    const float* W_mlp  = (const float*)d_in[3];
    const float* b_mlp  = (const float*)d_in[4];
    float* out = (float*)d_out;

    void *pa, *px, *pwq, *pwm, *ph, *pqo, *pko, *pvo;
    cudaGetSymbolAddress(&pa,  g_attn);
    cudaGetSymbolAddress(&px,  g_x);
    cudaGetSymbolAddress(&pwq, g_wq);
    cudaGetSymbolAddress(&pwm, g_wm);
    cudaGetSymbolAddress(&ph,  g_h);
    cudaGetSymbolAddress(&pqo, g_q);
    cudaGetSymbolAddress(&pko, g_k);
    cudaGetSymbolAddress(&pvo, g_v);
    float* gattn = (float*)pa;

    cudaFuncSetAttribute(tc_gemm7<true, false>,
                         cudaFuncAttributeMaxDynamicSharedMemorySize, GEMM_SMEM);
    cudaFuncSetAttribute(tc_gemm7<false, true>,
                         cudaFuncAttributeMaxDynamicSharedMemorySize, GEMM_SMEM);
    cudaFuncSetAttribute(flash7_kernel,
                         cudaFuncAttributeMaxDynamicSharedMemorySize, FLASH_SMEM);

    cudaStream_t s1;
    cudaStreamCreateWithFlags(&s1, cudaStreamNonBlocking);
    cudaEvent_t eLN, e1;
    cudaEventCreateWithFlags(&eLN, cudaEventDisableTiming);
    cudaEventCreateWithFlags(&e1, cudaEventDisableTiming);

    // ---- side stream: W_mlp convert up front ----
    convert_kernel<<<(HIDDEN * D_MODEL / 4) / 256, 256, 0, s1>>>(W_mlp, (__half*)pwm);

    // 0) convert W_qkv; 1) LN(inputs) -> fp16  (main)
    convert_kernel<<<(D_MODEL * QKV_OUT / 4) / 256, 256>>>(W_qkv, (__half*)pwq);
    ln_input_kernel<<<BT, 256>>>(inputs, (__half*)px);
    cudaEventRecord(eLN, 0);

    // ---- s1 branch: hidden-GEMM (GELU->fp16) then MLP ----
    cudaStreamWaitEvent(s1, eLN, 0);
    tc_gemm7<true, false><<<dim3(BT / 128, (QKV_OUT - QKV3) / 128), 256, GEMM_SMEM, s1>>>(
        (__half*)px, D_MODEL, (__half*)pwq, QKV_OUT,
        nullptr, 0, b_qkv, nullptr, (__half*)ph,
        nullptr, nullptr, nullptr, D_MODEL, QKV3 / 128);
    tc_gemm7<false, true><<<dim3(BT / 128, D_MODEL / 128), 256, GEMM_SMEM, s1>>>(
        (__half*)ph, HIDDEN, (__half*)pwm, D_MODEL,
        out, D_MODEL, b_mlp, inputs, nullptr,
        nullptr, nullptr, nullptr, HIDDEN, 0);
    cudaEventRecord(e1, s1);

    // ---- main branch: qkv-GEMM (fused head-LN, log2e-scaled q) then flash ----
    tc_gemm7<true, false><<<dim3(BT / 128, QKV3 / 128), 256, GEMM_SMEM>>>(
        (__half*)px, D_MODEL, (__half*)pwq, QKV_OUT,
        nullptr, 0, b_qkv, nullptr, (__half*)ph,
        (__half*)pqo, (__half*)pko, (__half*)pvo, D_MODEL, 0);
    flash7_kernel<<<dim3(8, BB * NUM_HEADS), 256, FLASH_SMEM>>>(
        (__half*)pqo, (__half*)pko, (__half*)pvo, gattn);

    // ---- join, then out += attn ----
    cudaStreamWaitEvent(0, e1, 0);
    attn_add_kernel<<<(BT * D_MODEL / 4) / 256, 256>>>(out, gattn);
}

// round 15
// speedup vs baseline: 1.0304x; 1.0017x over previous
#include <cuda_runtime.h>
#include <cuda_fp16.h>
#include <math.h>
#include <stdint.h>

#define D_MODEL   2048
#define NUM_HEADS 16
#define HEAD      128
#define FAN       4
#define QKV_OUT   (3 * D_MODEL + FAN * D_MODEL)   // 14336
#define HIDDEN    (FAN * D_MODEL)                 // 8192
#define BB        2
#define TT        2048
#define BT        (BB * TT)                       // 4096
#define QKV3      (3 * D_MODEL)                   // 6144

// ---------------- scratch (device globals) ---------------------------------
__device__ float  g_attn[(size_t)BT * D_MODEL];   // attention output scratch
__device__ __half g_x[(size_t)BT * D_MODEL];
__device__ __half g_wq[(size_t)D_MODEL * QKV_OUT];
__device__ __half g_wm[(size_t)HIDDEN * D_MODEL];
__device__ __half g_h[(size_t)BT * HIDDEN];
// head-major [b][h][t][d] q/k/v for flash
__device__ __half g_q[(size_t)BT * D_MODEL];
__device__ __half g_k[(size_t)BT * D_MODEL];
__device__ __half g_v[(size_t)BT * D_MODEL];

// ---------------- PTX helpers ----------------------------------------------
__device__ __forceinline__ uint32_t smem_u32(const void* p) {
    uint32_t a;
    asm("{ .reg .u64 t; cvta.to.shared.u64 t, %1; cvt.u32.u64 %0, t; }"
        : "=r"(a) : "l"(p));
    return a;
}
__device__ __forceinline__ void cp16(uint32_t dst, const void* src) {
    asm volatile("cp.async.cg.shared.global [%0], [%1], 16;" :: "r"(dst), "l"(src));
}
#define CP_COMMIT() asm volatile("cp.async.commit_group;")
#define CP_WAIT0()  asm volatile("cp.async.wait_group 0;")
#define CP_WAIT1()  asm volatile("cp.async.wait_group 1;")
#define CP_WAIT2()  asm volatile("cp.async.wait_group 2;")

__device__ __forceinline__ void ldsm_x4(uint32_t& r0, uint32_t& r1,
                                        uint32_t& r2, uint32_t& r3, uint32_t addr) {
    asm volatile("ldmatrix.sync.aligned.m8n8.x4.shared.b16 {%0,%1,%2,%3}, [%4];"
                 : "=r"(r0), "=r"(r1), "=r"(r2), "=r"(r3) : "r"(addr));
}
__device__ __forceinline__ void ldsm_x4t(uint32_t& r0, uint32_t& r1,
                                         uint32_t& r2, uint32_t& r3, uint32_t addr) {
    asm volatile("ldmatrix.sync.aligned.m8n8.x4.trans.shared.b16 {%0,%1,%2,%3}, [%4];"
                 : "=r"(r0), "=r"(r1), "=r"(r2), "=r"(r3) : "r"(addr));
}
__device__ __forceinline__ void mma_f16(float* d,
                                        uint32_t a0, uint32_t a1, uint32_t a2, uint32_t a3,
                                        uint32_t b0, uint32_t b1) {
    asm volatile(
        "mma.sync.aligned.m16n8k16.row.col.f32.f16.f16.f32 "
        "{%0,%1,%2,%3}, {%4,%5,%6,%7}, {%8,%9}, {%0,%1,%2,%3};"
        : "+f"(d[0]), "+f"(d[1]), "+f"(d[2]), "+f"(d[3])
        : "r"(a0), "r"(a1), "r"(a2), "r"(a3), "r"(b0), "r"(b1));
}
__device__ __forceinline__ uint32_t pack_h(float x, float y) {
    __half2 h = __float22half2_rn(make_float2(x, y));
    return *(uint32_t*)&h;
}
// two exps in one MUFU op (fp16x2, base-2)
__device__ __forceinline__ uint32_t ex2_f16x2(float a, float b) {
    uint32_t in = pack_h(a, b), out;
    asm("ex2.approx.f16x2 %0, %1;" : "=r"(out) : "r"(in));
    return out;
}
__device__ __forceinline__ float ex2f(float x) {
    float y; asm("ex2.approx.f32 %0, %1;" : "=f"(y) : "f"(x)); return y;
}
__device__ __forceinline__ float warp_sum(float v) {
    #pragma unroll
    for (int o = 16; o > 0; o >>= 1) v += __shfl_xor_sync(0xffffffffu, v, o);
    return v;
}
__device__ __forceinline__ float gelu_f(float x) {
    return 0.5f * x * (1.f + erff(x * 0.70710678118654752f));
}

// ---------------- 0) fp32 -> fp16 convert (weights) -------------------------
__global__ void convert_kernel(const float* __restrict__ in, __half* __restrict__ oh) {
    int idx = blockIdx.x * blockDim.x + threadIdx.x;
    float4 v = ((const float4*)in)[idx];
    ((uint2*)oh)[idx] = make_uint2(pack_h(v.x, v.y), pack_h(v.z, v.w));
}

// ---------------- 1) LayerNorm(inputs) -> fp16 ------------------------------
__global__ void ln_input_kernel(const float* __restrict__ in, __half* __restrict__ oh) {
    int row = blockIdx.x;
    const float4* src = (const float4*)(in + (size_t)row * D_MODEL);

    float4 v[2];
    float s = 0.f, sq = 0.f;
    #pragma unroll
    for (int i = 0; i < 2; i++) {
        v[i] = src[threadIdx.x + i * 256];
        s  += v[i].x + v[i].y + v[i].z + v[i].w;
        sq += v[i].x * v[i].x + v[i].y * v[i].y + v[i].z * v[i].z + v[i].w * v[i].w;
    }
    __shared__ float sh_s[8], sh_q[8];
    int lane = threadIdx.x & 31, wid = threadIdx.x >> 5;
    s = warp_sum(s); sq = warp_sum(sq);
    if (lane == 0) { sh_s[wid] = s; sh_q[wid] = sq; }
    __syncthreads();
    if (wid == 0) {
        float a = (lane < 8) ? sh_s[lane] : 0.f;
        float b = (lane < 8) ? sh_q[lane] : 0.f;
        a = warp_sum(a); b = warp_sum(b);
        if (lane == 0) { sh_s[0] = a; sh_q[0] = b; }
    }
    __syncthreads();
    float mean = sh_s[0] * (1.f / D_MODEL);
    float var  = sh_q[0] * (1.f / D_MODEL) - mean * mean;
    float r    = rsqrtf(var + 1e-5f);
    #pragma unroll
    for (int i = 0; i < 2; i++) {
        float a = (v[i].x - mean) * r, b = (v[i].y - mean) * r;
        float c = (v[i].z - mean) * r, d = (v[i].w - mean) * r;
        size_t o = (size_t)row * (D_MODEL / 4) + threadIdx.x + i * 256;
        ((uint2*)oh)[o] = make_uint2(pack_h(a, b), pack_h(c, d));
    }
}

// ============================================================================
// 2) 4-stage cp.async fp16 GEMM (round-7 mainloop). CTA 128x128, 8 warps
//    (32x64 warp tiles), kstage=32, 2 CTAs/SM. bn0 = column-block offset.
// ============================================================================
#define GSTAGE 16384
#define GEMM_SMEM (4 * GSTAGE)   // 64 KB

template<bool QKV, bool ADD_RES>
__global__ __launch_bounds__(256, 2)
void tc_gemm7(const __half* __restrict__ Ah, int lda,
              const __half* __restrict__ Bh, int ldb,
              float* __restrict__ C, int ldc,
              const float* __restrict__ bias,
              const float* __restrict__ res,
              __half* __restrict__ Hh,
              __half* __restrict__ Qo, __half* __restrict__ Ko,
              __half* __restrict__ Vo,
              int K, int bn0) {
    extern __shared__ char gsm[];
    const uint32_t smb = smem_u32(gsm);

    const int tid = threadIdx.x;
    const int l = tid & 31, w = tid >> 5;
    const int wm = (w & 3) * 32;
    const int wn = (w >> 2) * 64;
    const int bm = blockIdx.x * 128, bn = (blockIdx.y + bn0) * 128;

    const int ar = tid >> 1;
    const int ac0 = (tid & 1) * 2;
    const int br = tid >> 3;
    const int bc0 = (tid & 7) * 2;

    float acc[2][8][4];
    #pragma unroll
    for (int mt = 0; mt < 2; mt++)
        #pragma unroll
        for (int nt = 0; nt < 8; nt++)
            #pragma unroll
            for (int e = 0; e < 4; e++) acc[mt][nt][e] = 0.f;

    const int nkb = K / 32;

    auto issue = [&](int stage, int k0) {
        uint32_t sb = smb + stage * GSTAGE;
        #pragma unroll
        for (int j = 0; j < 2; j++) {
            int c = ac0 + j;
            cp16(sb + ar * 64 + 16 * (c ^ ((ar >> 1) & 3)),
                 Ah + (size_t)(bm + ar) * lda + k0 + c * 8);
        }
        #pragma unroll
        for (int j = 0; j < 2; j++) {
            int c = bc0 + j;
            cp16(sb + 8192 + br * 256 + 16 * ((c & 8) | ((c ^ br) & 7)),
                 Bh + (size_t)(k0 + br) * ldb + bn + c * 8);
        }
    };

    issue(0, 0);  CP_COMMIT();
    issue(1, 32); CP_COMMIT();
    issue(2, 64); CP_COMMIT();

    for (int kb = 0; kb < nkb; kb++) {
        int rem = nkb - 1 - kb;
        if (rem >= 2)      { CP_WAIT2(); }
        else if (rem == 1) { CP_WAIT1(); }
        else               { CP_WAIT0(); }
        __syncthreads();
        if (kb + 3 < nkb) { issue((kb + 3) & 3, (kb + 3) * 32); CP_COMMIT(); }

        uint32_t sb = smb + (kb & 3) * GSTAGE;
        #pragma unroll
        for (int ks = 0; ks < 2; ks++) {
            uint32_t A[2][4];
            #pragma unroll
            for (int mt = 0; mt < 2; mt++) {
                int r = wm + mt * 16 + (l & 15);
                int c = ks * 2 + (l >> 4);
                ldsm_x4(A[mt][0], A[mt][1], A[mt][2], A[mt][3],
                        sb + r * 64 + 16 * (c ^ ((r >> 1) & 3)));
            }
            uint32_t B[4][4];
            #pragma unroll
            for (int p = 0; p < 4; p++) {
                int g = (w >> 2) * 4 + p;
                int kk = ks * 16 + (l & 7) + ((l >> 3) & 1) * 8;
                int c = 2 * g + ((l >> 4) & 1);
                ldsm_x4t(B[p][0], B[p][1], B[p][2], B[p][3],
                         sb + 8192 + kk * 256 + 16 * ((c & 8) | ((c ^ kk) & 7)));
            }
            #pragma unroll
            for (int p = 0; p < 4; p++)
                #pragma unroll
                for (int mt = 0; mt < 2; mt++) {
                    mma_f16(acc[mt][p * 2],     A[mt][0], A[mt][1], A[mt][2], A[mt][3], B[p][0], B[p][1]);
                    mma_f16(acc[mt][p * 2 + 1], A[mt][0], A[mt][1], A[mt][2], A[mt][3], B[p][2], B[p][3]);
                }
        }
    }

    // ---- epilogue ----
    if (QKV && bn >= QKV3) {
        // hidden block: fused GELU -> fp16
        #pragma unroll
        for (int mt = 0; mt < 2; mt++) {
            int row0 = bm + wm + mt * 16 + (l >> 2);
            #pragma unroll
            for (int nt = 0; nt < 8; nt++) {
                int col = bn + wn + nt * 8 + (l & 3) * 2;
                int hcol = col - QKV3;
                float b0 = bias[col], b1 = bias[col + 1];
                float* d = acc[mt][nt];
                *(uint32_t*)(Hh + (size_t)row0 * HIDDEN + hcol) =
                    pack_h(gelu_f(d[0] + b0), gelu_f(d[1] + b1));
                *(uint32_t*)(Hh + (size_t)(row0 + 8) * HIDDEN + hcol) =
                    pack_h(gelu_f(d[2] + b0), gelu_f(d[3] + b1));
            }
        }
    } else if (QKV) {
        // q/k/v block: this CTA column block == exactly one head
        const int seg = bn >> 11;            // 0=q, 1=k, 2=v
        const int hd  = (bn >> 7) & 15;      // head index
        __half* dst = (seg == 0) ? Qo : (seg == 1) ? Ko : Vo;

        #pragma unroll
        for (int mt = 0; mt < 2; mt++)
            #pragma unroll
            for (int nt = 0; nt < 8; nt++) {
                int col = bn + wn + nt * 8 + (l & 3) * 2;
                float b0 = bias[col], b1 = bias[col + 1];
                float* d = acc[mt][nt];
                d[0] += b0; d[1] += b1; d[2] += b0; d[3] += b1;
            }

        float mean_[4], rr_[4];
        if (seg < 2) {
            float ps[4] = {0.f, 0.f, 0.f, 0.f}, pq[4] = {0.f, 0.f, 0.f, 0.f};
            #pragma unroll
            for (int mt = 0; mt < 2; mt++)
                #pragma unroll
                for (int nt = 0; nt < 8; nt++) {
                    float* d = acc[mt][nt];
                    ps[mt * 2]     += d[0] + d[1];
                    pq[mt * 2]     += d[0] * d[0] + d[1] * d[1];
                    ps[mt * 2 + 1] += d[2] + d[3];
                    pq[mt * 2 + 1] += d[2] * d[2] + d[3] * d[3];
                }
            #pragma unroll
            for (int o = 1; o < 4; o <<= 1)
                #pragma unroll
                for (int i = 0; i < 4; i++) {
                    ps[i] += __shfl_xor_sync(0xffffffffu, ps[i], o);
                    pq[i] += __shfl_xor_sync(0xffffffffu, pq[i], o);
                }
            float* red = (float*)gsm;
            __syncthreads();
            if ((l & 3) == 0) {
                #pragma unroll
                for (int i = 0; i < 4; i++) {
                    int r = wm + (i >> 1) * 16 + (i & 1) * 8 + (l >> 2);
                    red[(w >> 2) * 128 + r]       = ps[i];
                    red[256 + (w >> 2) * 128 + r] = pq[i];
                }
            }
            __syncthreads();
            #pragma unroll
            for (int i = 0; i < 4; i++) {
                int r = wm + (i >> 1) * 16 + (i & 1) * 8 + (l >> 2);
                float tot = red[r] + red[128 + r];
                float sqt = red[256 + r] + red[256 + 128 + r];
                float mean = tot * (1.f / HEAD);
                float var  = sqt * (1.f / HEAD) - mean * mean;
                float rr = rsqrtf(var + 1e-5f);
                // q: fold 1/sqrt(HEAD) AND log2(e)  (softmax works in base-2)
                if (seg == 0) rr *= 0.08838834764831845f * 1.4426950408889634f;
                mean_[i] = mean; rr_[i] = rr;
            }
        } else {
            #pragma unroll
            for (int i = 0; i < 4; i++) { mean_[i] = 0.f; rr_[i] = 1.f; }
        }

        #pragma unroll
        for (int mt = 0; mt < 2; mt++) {
            #pragma unroll
            for (int half = 0; half < 2; half++) {
                int i = mt * 2 + half;
                int r = wm + mt * 16 + half * 8 + (l >> 2);
                int token = bm + r;
                int b = token >> 11, tt = token & 2047;
                __half* rowp = dst + ((((size_t)b * 16 + hd) * 2048 + tt) * 128);
                #pragma unroll
                for (int nt = 0; nt < 8; nt++) {
                    int dcol = wn + nt * 8 + (l & 3) * 2;
                    float* d = acc[mt][nt];
                    float v0 = (d[half * 2]     - mean_[i]) * rr_[i];
                    float v1 = (d[half * 2 + 1] - mean_[i]) * rr_[i];
                    *(uint32_t*)(rowp + dcol) = pack_h(v0, v1);
                }
            }
        }
    } else {
        #pragma unroll
        for (int mt = 0; mt < 2; mt++) {
            int row0 = bm + wm + mt * 16 + (l >> 2);
            #pragma unroll
            for (int nt = 0; nt < 8; nt++) {
                int col = bn + wn + nt * 8 + (l & 3) * 2;
                float b0 = bias[col], b1 = bias[col + 1];
                float* d = acc[mt][nt];
                float2 o0 = make_float2(d[0] + b0, d[1] + b1);
                float2 o1 = make_float2(d[2] + b0, d[3] + b1);
                if (ADD_RES) {
                    float2 r0 = *(const float2*)(res + (size_t)row0 * ldc + col);
                    float2 r1 = *(const float2*)(res + (size_t)(row0 + 8) * ldc + col);
                    o0.x += r0.x; o0.y += r0.y;
                    o1.x += r1.x; o1.y += r1.y;
                }
                *(float2*)(C + (size_t)row0 * ldc + col) = o0;
                *(float2*)(C + (size_t)(row0 + 8) * ldc + col) = o1;
            }
        }
    }
}

// ============================================================================
// 3) flash v8: lane-partial L (no per-iter sum shfl) + warp-voted rescale
//    skip, base-2 softmax with ex2.approx.f16x2, qt-paired work balance.
// ============================================================================
#define FLASH_SMEM 98304   // Q 32KB + 2 stages x (K 16KB + V 16KB)

__global__ __launch_bounds__(256, 2)
void flash8_kernel(const __half* __restrict__ qh, const __half* __restrict__ kh,
                   const __half* __restrict__ vh, float* __restrict__ attn) {
    extern __shared__ char fsm[];
    const uint32_t sb = smem_u32(fsm);
    const int tid = threadIdx.x;
    const int l = tid & 31, w = tid >> 5;
    const int bx = blockIdx.x;
    const int bh = blockIdx.y;
    const size_t hbase = (size_t)bh * 2048 * 128;

    auto issue_kv = [&](int stage, int kt) {
        uint32_t stb = sb + 32768 + stage * 32768;
        int r = tid >> 2, q4 = tid & 3;
        const __half* pk = kh + hbase + (size_t)(kt * 64 + r) * 128;
        const __half* pv = vh + hbase + (size_t)(kt * 64 + r) * 128;
        #pragma unroll
        for (int j = 0; j < 4; j++) {
            int c = q4 * 4 + j;
            uint32_t sw = r * 256 + 16 * ((c & 8) | ((c ^ r) & 7));
            cp16(stb + sw,         pk + c * 8);
            cp16(stb + 16384 + sw, pv + c * 8);
        }
    };

    #pragma unroll 1
    for (int pair = 0; pair < 2; pair++) {
        const int qt = pair ? (15 - bx) : bx;

        if (pair) __syncthreads();

        // ---- issue Q (128 rows x 256B) ----
        {
            int row = tid >> 1, half = tid & 1;
            const __half* sq = qh + hbase + (size_t)(qt * 128 + row) * 128;
            #pragma unroll
            for (int j = 0; j < 8; j++) {
                int c = half * 8 + j;
                cp16(sb + row * 256 + 16 * ((c & 8) | ((c ^ row) & 7)), sq + c * 8);
            }
        }
        CP_COMMIT();
        issue_kv(0, 0);
        CP_COMMIT();

        float O_[16][4];
        #pragma unroll
        for (int t = 0; t < 16; t++)
            #pragma unroll
            for (int e = 0; e < 4; e++) O_[t][e] = 0.f;
        float M0 = -INFINITY, M1 = -INFINITY, L0 = 0.f, L1 = 0.f;
        const int ktmax = 2 * qt + 1;

        for (int kt = 0; kt <= ktmax; kt++) {
            CP_WAIT0();
            __syncthreads();
            if (kt < ktmax) { issue_kv((kt + 1) & 1, kt + 1); CP_COMMIT(); }

            uint32_t stb = sb + 32768 + (kt & 1) * 32768;

            // ---- S = Q K^T (S in log2 domain: log2e folded into q) ----
            float s_[8][4];
            #pragma unroll
            for (int t = 0; t < 8; t++)
                #pragma unroll
                for (int e = 0; e < 4; e++) s_[t][e] = 0.f;

            #pragma unroll
            for (int ks = 0; ks < 8; ks++) {
                int qr = w * 16 + (l & 15);
                int qc = ks * 2 + (l >> 4);
                uint32_t q0, q1, q2, q3;
                ldsm_x4(q0, q1, q2, q3, sb + qr * 256 + 16 * ((qc & 8) | ((qc ^ qr) & 7)));
                #pragma unroll
                for (int g = 0; g < 4; g++) {
                    int kr = g * 16 + (l & 7) + ((l >> 4) & 1) * 8;
                    int kc = ks * 2 + ((l >> 3) & 1);
                    uint32_t b0, b1, b2, b3;
                    ldsm_x4(b0, b1, b2, b3, stb + kr * 256 + 16 * ((kc & 8) | ((kc ^ kr) & 7)));
                    mma_f16(s_[2 * g],     q0, q1, q2, q3, b0, b1);
                    mma_f16(s_[2 * g + 1], q0, q1, q2, q3, b2, b3);
                }
            }

            if (kt >= 2 * qt) {
                int qr0 = qt * 128 + w * 16 + (l >> 2);
                int qr1 = qr0 + 8;
                #pragma unroll
                for (int t = 0; t < 8; t++) {
                    int kc = kt * 64 + t * 8 + (l & 3) * 2;
                    if (kc     > qr0) s_[t][0] = -INFINITY;
                    if (kc + 1 > qr0) s_[t][1] = -INFINITY;
                    if (kc     > qr1) s_[t][2] = -INFINITY;
                    if (kc + 1 > qr1) s_[t][3] = -INFINITY;
                }
            }

            // ---- online softmax (base-2), lane-partial L ----
            float m0 = -INFINITY, m1 = -INFINITY;
            #pragma unroll
            for (int t = 0; t < 8; t++) {
                m0 = fmaxf(m0, fmaxf(s_[t][0], s_[t][1]));
                m1 = fmaxf(m1, fmaxf(s_[t][2], s_[t][3]));
            }
            #pragma unroll
            for (int o = 1; o < 4; o <<= 1) {
                m0 = fmaxf(m0, __shfl_xor_sync(0xffffffffu, m0, o));
                m1 = fmaxf(m1, __shfl_xor_sync(0xffffffffu, m1, o));
            }
            float nm0 = fmaxf(M0, m0), nm1 = fmaxf(M1, m1);
            bool need = (nm0 > M0) || (nm1 > M1);
            float corr0 = ex2f(M0 - nm0), corr1 = ex2f(M1 - nm1);
            M0 = nm0; M1 = nm1;

            // P = 2^(s - m) as fp16 pairs; L kept lane-partial (no shfl here)
            uint32_t P[8][2];
            float ps0 = 0.f, ps1 = 0.f;
            #pragma unroll
            for (int t = 0; t < 8; t++) {
                uint32_t p0 = ex2_f16x2(s_[t][0] - nm0, s_[t][1] - nm0);
                uint32_t p1 = ex2_f16x2(s_[t][2] - nm1, s_[t][3] - nm1);
                P[t][0] = p0; P[t][1] = p1;
                float2 f0 = __half22float2(*(__half2*)&p0);
                float2 f1 = __half22float2(*(__half2*)&p1);
                ps0 += f0.x + f0.y;
                ps1 += f1.x + f1.y;
            }
            L0 = L0 * corr0 + ps0;
            L1 = L1 * corr1 + ps1;

            // O rescale only when some row max moved (corr==1 exactly otherwise)
            if (__any_sync(0xffffffffu, need)) {
                #pragma unroll
                for (int t = 0; t < 16; t++) {
                    O_[t][0] *= corr0; O_[t][1] *= corr0;
                    O_[t][2] *= corr1; O_[t][3] *= corr1;
                }
            }

            // ---- O += P V ----
            #pragma unroll
            for (int s8 = 0; s8 < 4; s8++) {
                uint32_t ph[4];
                ph[0] = P[2 * s8][0];
                ph[1] = P[2 * s8][1];
                ph[2] = P[2 * s8 + 1][0];
                ph[3] = P[2 * s8 + 1][1];
                #pragma unroll
                for (int g = 0; g < 8; g++) {
                    int vr = s8 * 16 + (l & 7) + ((l >> 3) & 1) * 8;
                    int vc = 2 * g + ((l >> 4) & 1);
                    uint32_t v0, v1, v2, v3;
                    ldsm_x4t(v0, v1, v2, v3,
                             stb + 16384 + vr * 256 + 16 * ((vc & 8) | ((vc ^ vr) & 7)));
                    mma_f16(O_[2 * g],     ph[0], ph[1], ph[2], ph[3], v0, v1);
                    mma_f16(O_[2 * g + 1], ph[0], ph[1], ph[2], ph[3], v2, v3);
                }
            }
        }

        // ---- reduce lane-partial L across the 4-lane row group ----
        #pragma unroll
        for (int o = 1; o < 4; o <<= 1) {
            L0 += __shfl_xor_sync(0xffffffffu, L0, o);
            L1 += __shfl_xor_sync(0xffffffffu, L1, o);
        }

        // ---- epilogue: attn = O / L ----
        int b = bh >> 4, h = bh & 15;
        float inv0 = 1.f / L0, inv1 = 1.f / L1;
        int token = qt * 128 + w * 16 + (l >> 2);
        float* row0p = attn + (size_t)(b * TT + token) * D_MODEL + h * HEAD;
        float* row1p = row0p + (size_t)8 * D_MODEL;
        #pragma unroll
        for (int t = 0; t < 16; t++) {
            int col = t * 8 + (l & 3) * 2;
            *(float2*)(row0p + col) = make_float2(O_[t][0] * inv0, O_[t][1] * inv0);
            *(float2*)(row1p + col) = make_float2(O_[t][2] * inv1, O_[t][3] * inv1);
        }
    }
}

// ---------------- 4) out += attn --------------------------------------------
__global__ void attn_add_kernel(float* __restrict__ out, const float* __restrict__ attn) {
    int idx = blockIdx.x * blockDim.x + threadIdx.x;
    float4 o = ((float4*)out)[idx];
    float4 a = ((const float4*)attn)[idx];
    o.x += a.x; o.y += a.y; o.z += a.z; o.w += a.w;
    ((float4*)out)[idx] = o;
}

// ---------------- launch (round-13 topology, capture-safe) ------------------
extern "C" void kernel_launch(void* const* d_in, const int* in_sizes, int n_in,
                              void* d_out, int out_size) {
    const float* inputs = (const float*)d_in[0];
    const float* W_qkv  = (const float*)d_in[1];
    const float* b_qkv  = (const float*)d_in[2];
    const float* W_mlp  = (const float*)d_in[3];
    const float* b_mlp  = (const float*)d_in[4];
    float* out = (float*)d_out;

    void *pa, *px, *pwq, *pwm, *ph, *pqo, *pko, *pvo;
    cudaGetSymbolAddress(&pa,  g_attn);
    cudaGetSymbolAddress(&px,  g_x);
    cudaGetSymbolAddress(&pwq, g_wq);
    cudaGetSymbolAddress(&pwm, g_wm);
    cudaGetSymbolAddress(&ph,  g_h);
    cudaGetSymbolAddress(&pqo, g_q);
    cudaGetSymbolAddress(&pko, g_k);
    cudaGetSymbolAddress(&pvo, g_v);
    float* gattn = (float*)pa;

    cudaFuncSetAttribute(tc_gemm7<true, false>,
                         cudaFuncAttributeMaxDynamicSharedMemorySize, GEMM_SMEM);
    cudaFuncSetAttribute(tc_gemm7<false, true>,
                         cudaFuncAttributeMaxDynamicSharedMemorySize, GEMM_SMEM);
    cudaFuncSetAttribute(flash8_kernel,
                         cudaFuncAttributeMaxDynamicSharedMemorySize, FLASH_SMEM);

    cudaStream_t s1;
    cudaStreamCreateWithFlags(&s1, cudaStreamNonBlocking);
    cudaEvent_t eLN, e1;
    cudaEventCreateWithFlags(&eLN, cudaEventDisableTiming);
    cudaEventCreateWithFlags(&e1, cudaEventDisableTiming);

    // ---- side stream: W_mlp convert up front ----
    convert_kernel<<<(HIDDEN * D_MODEL / 4) / 256, 256, 0, s1>>>(W_mlp, (__half*)pwm);

    // 0) convert W_qkv; 1) LN(inputs) -> fp16  (main)
    convert_kernel<<<(D_MODEL * QKV_OUT / 4) / 256, 256>>>(W_qkv, (__half*)pwq);
    ln_input_kernel<<<BT, 256>>>(inputs, (__half*)px);
    cudaEventRecord(eLN, 0);

    // ---- s1 branch: hidden-GEMM (GELU->fp16) then MLP ----
    cudaStreamWaitEvent(s1, eLN, 0);
    tc_gemm7<true, false><<<dim3(BT / 128, (QKV_OUT - QKV3) / 128), 256, GEMM_SMEM, s1>>>(
        (__half*)px, D_MODEL, (__half*)pwq, QKV_OUT,
        nullptr, 0, b_qkv, nullptr, (__half*)ph,
        nullptr, nullptr, nullptr, D_MODEL, QKV3 / 128);
    tc_gemm7<false, true><<<dim3(BT / 128, D_MODEL / 128), 256, GEMM_SMEM, s1>>>(
        (__half*)ph, HIDDEN, (__half*)pwm, D_MODEL,
        out, D_MODEL, b_mlp, inputs, nullptr,
        nullptr, nullptr, nullptr, HIDDEN, 0);
    cudaEventRecord(e1, s1);

    // ---- main branch: qkv-GEMM (fused head-LN, log2e-scaled q) then flash ----
    tc_gemm7<true, false><<<dim3(BT / 128, QKV3 / 128), 256, GEMM_SMEM>>>(
        (__half*)px, D_MODEL, (__half*)pwq, QKV_OUT,
        nullptr, 0, b_qkv, nullptr, (__half*)ph,
        (__half*)pqo, (__half*)pko, (__half*)pvo, D_MODEL, 0);
    flash8_kernel<<<dim3(8, BB * NUM_HEADS), 256, FLASH_SMEM>>>(
        (__half*)pqo, (__half*)pko, (__half*)pvo, gattn);

    // ---- join, then out += attn ----
    cudaStreamWaitEvent(0, e1, 0);
    attn_add_kernel<<<(BT * D_MODEL / 4) / 256, 256>>>(out, gattn);
}